// round 1
// baseline (speedup 1.0000x reference)
#include <cuda_runtime.h>
#include <math.h>

#define NN 50000
#define DD 128
#define EE 800000
#define ET (EE + NN)

#define TM 64
#define TN 256
#define XS_PITCH 68
#define WS_PITCH 260
#define GEMM_SMEM ((DD * XS_PITCH + DD * WS_PITCH) * 4)

// Scratch (allocation-free rule: __device__ globals)
__device__ float g_xl[NN * DD];
__device__ float g_xr[NN * DD];
__device__ float g_h[NN * DD];
__device__ int g_rowptr[NN + 1];
__device__ int g_deg[NN];
__device__ int g_fill[NN];
__device__ int g_srcs[ET];
__device__ int g_is64;

// ---------------------------------------------------------------------------
// edge_index dtype detection: int64 values are all < NN (high word 0);
// int32 data reinterpreted as int64 yields values >= 2^32 w.h.p.
// ---------------------------------------------------------------------------
__global__ void k_detect(const void* e) {
    if (threadIdx.x == 0 && blockIdx.x == 0) {
        const long long* p = (const long long*)e;
        int ok = 1;
        for (int i = 0; i < 16; i++) {
            long long v = p[i];
            if (v < 0 || v >= NN) ok = 0;
        }
        g_is64 = ok;
    }
}

__device__ __forceinline__ int load_idx(const void* e, long long pos, int is64) {
    return is64 ? (int)((const long long*)e)[pos] : ((const int*)e)[pos];
}

__global__ void k_zero_cnt() {
    int i = blockIdx.x * blockDim.x + threadIdx.x;
    if (i < NN) { g_deg[i] = 0; g_fill[i] = 0; }
}

__global__ void k_hist(const void* __restrict__ eidx) {
    int e = blockIdx.x * blockDim.x + threadIdx.x;
    if (e >= ET) return;
    int is64 = g_is64;
    int dst = (e < EE) ? load_idx(eidx, (long long)EE + e, is64) : (e - EE);
    atomicAdd(&g_deg[dst], 1);
}

// Exclusive scan of g_deg into g_rowptr (single block, 1024 threads).
__global__ void k_scan() {
    __shared__ int sums[1024];
    const int t = threadIdx.x;
    const int CH = (NN + 1 + 1023) / 1024;  // 50
    int begin = t * CH;
    int s = 0;
#pragma unroll 5
    for (int i = begin; i < begin + CH; i++)
        if (i < NN) s += g_deg[i];
    sums[t] = s;
    __syncthreads();
    for (int off = 1; off < 1024; off <<= 1) {
        int x = (t >= off) ? sums[t - off] : 0;
        __syncthreads();
        sums[t] += x;
        __syncthreads();
    }
    int base = sums[t] - s;  // exclusive prefix across threads
    for (int i = begin; i < begin + CH; i++) {
        if (i <= NN) {
            g_rowptr[i] = base;
            if (i < NN) base += g_deg[i];
        }
    }
}

__global__ void k_scatter(const void* __restrict__ eidx) {
    int e = blockIdx.x * blockDim.x + threadIdx.x;
    if (e >= ET) return;
    int is64 = g_is64;
    int s, d;
    if (e < EE) {
        s = load_idx(eidx, e, is64);
        d = load_idx(eidx, (long long)EE + e, is64);
    } else {
        s = d = e - EE;
    }
    int pos = atomicAdd(&g_fill[d], 1);
    g_srcs[g_rowptr[d] + pos] = s;
}

// ---------------------------------------------------------------------------
// Fused GEMM: xl = h @ Wl^T, xr = h @ Wr^T. Block tile 64 rows x 256 cols
// (cols 0..127 -> xl, 128..255 -> xr). W transposed into smem for block life.
// ---------------------------------------------------------------------------
__global__ void __launch_bounds__(256, 1)
k_gemm(const float* __restrict__ hin,
       const float* __restrict__ Wl,
       const float* __restrict__ Wr) {
    extern __shared__ float sm[];
    float* xs = sm;                   // [128][XS_PITCH] : xs[k][m]
    float* ws = sm + DD * XS_PITCH;   // [128][WS_PITCH] : ws[k][j]

    const int tid = threadIdx.x;
    const int lane = tid & 31;
    const int warp = tid >> 5;
    const int row0 = blockIdx.x * TM;

    // Load W (both matrices) transposed: ws[k][j] = W[j][k]
    for (int j = warp; j < TN; j += 8) {
        const float* wsrc = (j < DD) ? (Wl + j * DD) : (Wr + (j - DD) * DD);
        float4 g = *(const float4*)(wsrc + lane * 4);
        ws[(lane * 4 + 0) * WS_PITCH + j] = g.x;
        ws[(lane * 4 + 1) * WS_PITCH + j] = g.y;
        ws[(lane * 4 + 2) * WS_PITCH + j] = g.z;
        ws[(lane * 4 + 3) * WS_PITCH + j] = g.w;
    }
    // Load x tile transposed: xs[k][m] = hin[row0+m][k]
    for (int m = warp; m < TM; m += 8) {
        int row = row0 + m;
        float4 g = make_float4(0.f, 0.f, 0.f, 0.f);
        if (row < NN) g = *(const float4*)(hin + (size_t)row * DD + lane * 4);
        xs[(lane * 4 + 0) * XS_PITCH + m] = g.x;
        xs[(lane * 4 + 1) * XS_PITCH + m] = g.y;
        xs[(lane * 4 + 2) * XS_PITCH + m] = g.z;
        xs[(lane * 4 + 3) * XS_PITCH + m] = g.w;
    }
    __syncthreads();

    const int warp_m = warp >> 2;       // 0..1
    const int warp_n = warp & 3;        // 0..3
    const int lane_m = lane >> 3;       // 0..3
    const int lane_n = lane & 7;        // 0..7
    const int rbase = warp_m * 32 + lane_m * 8;
    const int cbase = warp_n * 64 + lane_n * 8;

    float acc[8][8];
#pragma unroll
    for (int i = 0; i < 8; i++)
#pragma unroll
        for (int j = 0; j < 8; j++) acc[i][j] = 0.f;

#pragma unroll 4
    for (int k = 0; k < DD; k++) {
        float4 a0 = *(const float4*)&xs[k * XS_PITCH + rbase];
        float4 a1 = *(const float4*)&xs[k * XS_PITCH + rbase + 4];
        float4 b0 = *(const float4*)&ws[k * WS_PITCH + cbase];
        float4 b1 = *(const float4*)&ws[k * WS_PITCH + cbase + 4];
        float a[8] = {a0.x, a0.y, a0.z, a0.w, a1.x, a1.y, a1.z, a1.w};
        float b[8] = {b0.x, b0.y, b0.z, b0.w, b1.x, b1.y, b1.z, b1.w};
#pragma unroll
        for (int i = 0; i < 8; i++)
#pragma unroll
            for (int j = 0; j < 8; j++) acc[i][j] += a[i] * b[j];
    }

    const bool isL = (cbase < DD);
    float* outp = isL ? g_xl : g_xr;
    const int cc = isL ? cbase : (cbase - DD);
#pragma unroll
    for (int i = 0; i < 8; i++) {
        int row = row0 + rbase + i;
        if (row < NN) {
            float4 o0 = make_float4(acc[i][0], acc[i][1], acc[i][2], acc[i][3]);
            float4 o1 = make_float4(acc[i][4], acc[i][5], acc[i][6], acc[i][7]);
            *(float4*)(outp + (size_t)row * DD + cc) = o0;
            *(float4*)(outp + (size_t)row * DD + cc + 4) = o1;
        }
    }
}

// ---------------------------------------------------------------------------
// GATv2 aggregation, warp per destination node, online softmax single pass.
// out[d] = gelu( sum_j softmax_j(att . leakyrelu(xl[s_j]+xr[d])) * xl[s_j] + b )
// ---------------------------------------------------------------------------
__device__ __forceinline__ float gelu_exact(float x) {
    return 0.5f * x * (1.f + erff(x * 0.70710678118654752440f));
}

__global__ void __launch_bounds__(256)
k_agg(const float* __restrict__ att,
      const float* __restrict__ bias,
      float* __restrict__ hout) {
    const int gw = (blockIdx.x * blockDim.x + threadIdx.x) >> 5;
    const int lane = threadIdx.x & 31;
    if (gw >= NN) return;
    const int d4 = lane * 4;

    const float4 xr4 = *(const float4*)(g_xr + (size_t)gw * DD + d4);
    const float4 at4 = *(const float4*)(att + d4);

    const int p0 = g_rowptr[gw];
    const int p1 = g_rowptr[gw + 1];

    float m = __int_as_float(0xff800000);  // -inf
    float denom = 0.f;
    float ax = 0.f, ay = 0.f, az = 0.f, aw = 0.f;

    for (int p = p0; p < p1; p++) {
        int s = g_srcs[p];
        const float4 v = *(const float4*)(g_xl + (size_t)s * DD + d4);
        float t0 = v.x + xr4.x; t0 = t0 > 0.f ? t0 : 0.2f * t0;
        float t1 = v.y + xr4.y; t1 = t1 > 0.f ? t1 : 0.2f * t1;
        float t2 = v.z + xr4.z; t2 = t2 > 0.f ? t2 : 0.2f * t2;
        float t3 = v.w + xr4.w; t3 = t3 > 0.f ? t3 : 0.2f * t3;
        float e = t0 * at4.x + t1 * at4.y + t2 * at4.z + t3 * at4.w;
        e += __shfl_xor_sync(0xffffffffu, e, 16);
        e += __shfl_xor_sync(0xffffffffu, e, 8);
        e += __shfl_xor_sync(0xffffffffu, e, 4);
        e += __shfl_xor_sync(0xffffffffu, e, 2);
        e += __shfl_xor_sync(0xffffffffu, e, 1);

        float mn = fmaxf(m, e);
        float corr = expf(m - mn);   // exp(-inf)=0 on first edge
        float w = expf(e - mn);
        denom = denom * corr + w;
        ax = ax * corr + w * v.x;
        ay = ay * corr + w * v.y;
        az = az * corr + w * v.z;
        aw = aw * corr + w * v.w;
        m = mn;
    }

    const float inv = 1.f / denom;
    const float4 b4 = *(const float4*)(bias + d4);
    float4 o;
    o.x = gelu_exact(ax * inv + b4.x);
    o.y = gelu_exact(ay * inv + b4.y);
    o.z = gelu_exact(az * inv + b4.z);
    o.w = gelu_exact(aw * inv + b4.w);
    *(float4*)(hout + (size_t)gw * DD + d4) = o;
}

// ---------------------------------------------------------------------------
extern "C" void kernel_launch(void* const* d_in, const int* in_sizes, int n_in,
                              void* d_out, int out_size) {
    const float* x = (const float*)d_in[0];
    const void* eidx = d_in[1];
    const float* Wl[3] = {(const float*)d_in[2], (const float*)d_in[6], (const float*)d_in[10]};
    const float* Wr[3] = {(const float*)d_in[3], (const float*)d_in[7], (const float*)d_in[11]};
    const float* at[3] = {(const float*)d_in[4], (const float*)d_in[8], (const float*)d_in[12]};
    const float* bi[3] = {(const float*)d_in[5], (const float*)d_in[9], (const float*)d_in[13]};

    void* p_h_v = nullptr;
    cudaGetSymbolAddress(&p_h_v, g_h);
    float* p_h = (float*)p_h_v;

    cudaFuncSetAttribute(k_gemm, cudaFuncAttributeMaxDynamicSharedMemorySize, GEMM_SMEM);

    // Build CSR by destination (same graph for all 3 layers)
    k_detect<<<1, 32>>>(eidx);
    k_zero_cnt<<<(NN + 255) / 256, 256>>>();
    k_hist<<<(ET + 255) / 256, 256>>>(eidx);
    k_scan<<<1, 1024>>>();
    k_scatter<<<(ET + 255) / 256, 256>>>(eidx);

    for (int l = 0; l < 3; l++) {
        const float* hin = (l == 0) ? x : p_h;
        float* hout = (l == 2) ? (float*)d_out : p_h;
        k_gemm<<<(NN + TM - 1) / TM, 256, GEMM_SMEM>>>(hin, Wl[l], Wr[l]);
        k_agg<<<(NN * 32 + 255) / 256, 256>>>(at[l], bi[l], hout);
    }
}

// round 2
// speedup vs baseline: 2.0584x; 2.0584x over previous
#include <cuda_runtime.h>
#include <math.h>

#define NN 50000
#define DD 128
#define EE 800000
#define ET (EE + NN)

#define TM 64
#define TN 256
#define KP 132                      // smem row pitch (floats): 128 + 4 pad
#define GEMM_SMEM ((TM + TN) * KP * 4)   // 168960 B

#define SCB 1024
#define NBLK ((NN + SCB - 1) / SCB) // 49

// Scratch (allocation-free rule: __device__ globals)
__device__ float g_xl[NN * DD];
__device__ float g_xr[NN * DD];
__device__ float g_h[NN * DD];
__device__ int g_rowptr[NN + 1];
__device__ int g_deg[NN];
__device__ int g_fill[NN];
__device__ int g_srcs[ET];
__device__ int g_part[NBLK];
__device__ int g_is64;

// ---------------------------------------------------------------------------
// edge_index dtype detection (int64 vs int32 under jax x64-disabled)
// ---------------------------------------------------------------------------
__global__ void k_detect(const void* e) {
    if (threadIdx.x == 0 && blockIdx.x == 0) {
        const long long* p = (const long long*)e;
        int ok = 1;
        for (int i = 0; i < 16; i++) {
            long long v = p[i];
            if (v < 0 || v >= NN) ok = 0;
        }
        g_is64 = ok;
    }
}

__device__ __forceinline__ int load_idx(const void* e, long long pos, int is64) {
    return is64 ? (int)((const long long*)e)[pos] : ((const int*)e)[pos];
}

__global__ void k_zero_cnt() {
    int i = blockIdx.x * blockDim.x + threadIdx.x;
    if (i < NN) { g_deg[i] = 0; g_fill[i] = 0; }
}

__global__ void k_hist(const void* __restrict__ eidx) {
    int e = blockIdx.x * blockDim.x + threadIdx.x;
    if (e >= ET) return;
    int is64 = g_is64;
    int dst = (e < EE) ? load_idx(eidx, (long long)EE + e, is64) : (e - EE);
    atomicAdd(&g_deg[dst], 1);
}

// ---- multi-block exclusive scan of g_deg -> g_rowptr ----------------------
__global__ void k_scan1() {
    __shared__ int wsum[32];
    int i = blockIdx.x * SCB + threadIdx.x;
    int lane = threadIdx.x & 31, wid = threadIdx.x >> 5;
    int v = (i < NN) ? g_deg[i] : 0;
#pragma unroll
    for (int o = 1; o < 32; o <<= 1) v += __shfl_down_sync(~0u, v, o);
    if (lane == 0) wsum[wid] = v;
    __syncthreads();
    if (wid == 0) {
        int s = wsum[lane];
#pragma unroll
        for (int o = 1; o < 32; o <<= 1) s += __shfl_down_sync(~0u, s, o);
        if (lane == 0) g_part[blockIdx.x] = s;
    }
}

__global__ void k_scan2() {
    if (threadIdx.x == 0) {
        int run = 0;
        for (int b = 0; b < NBLK; b++) { int v = g_part[b]; g_part[b] = run; run += v; }
        g_rowptr[NN] = ET;
    }
}

__global__ void k_scan3() {
    __shared__ int wsum[32];
    int i = blockIdx.x * SCB + threadIdx.x;
    int lane = threadIdx.x & 31, wid = threadIdx.x >> 5;
    int v0 = (i < NN) ? g_deg[i] : 0;
    int v = v0;
#pragma unroll
    for (int o = 1; o < 32; o <<= 1) {
        int n = __shfl_up_sync(~0u, v, o);
        if (lane >= o) v += n;
    }
    if (lane == 31) wsum[wid] = v;
    __syncthreads();
    if (wid == 0) {
        int s = wsum[lane];
#pragma unroll
        for (int o = 1; o < 32; o <<= 1) {
            int n = __shfl_up_sync(~0u, s, o);
            if (lane >= o) s += n;
        }
        wsum[lane] = s;
    }
    __syncthreads();
    int excl = v - v0 + (wid ? wsum[wid - 1] : 0);
    if (i < NN) g_rowptr[i] = g_part[blockIdx.x] + excl;
}

__global__ void k_scatter(const void* __restrict__ eidx) {
    int e = blockIdx.x * blockDim.x + threadIdx.x;
    if (e >= ET) return;
    int is64 = g_is64;
    int s, d;
    if (e < EE) {
        s = load_idx(eidx, e, is64);
        d = load_idx(eidx, (long long)EE + e, is64);
    } else {
        s = d = e - EE;
    }
    int pos = atomicAdd(&g_fill[d], 1);
    g_srcs[g_rowptr[d] + pos] = s;
}

// ---------------------------------------------------------------------------
// Fused GEMM: xl = h @ Wl^T, xr = h @ Wr^T.
// Natural row-major smem (no transposes, conflict-free), packed f32x2 FFMA.
// Block: 64 rows x 256 outputs. Thread: 8x8 outputs, j strided by 8.
// ---------------------------------------------------------------------------
typedef unsigned long long u64;

__device__ __forceinline__ void ffma2(u64& acc, u64 a, u64 b) {
    asm("fma.rn.f32x2 %0, %1, %2, %0;" : "+l"(acc) : "l"(a), "l"(b));
}

__global__ void __launch_bounds__(256, 1)
k_gemm(const float* __restrict__ hin,
       const float* __restrict__ Wl,
       const float* __restrict__ Wr) {
    extern __shared__ float sm[];
    float* xs = sm;             // [TM][KP]
    float* ws = sm + TM * KP;   // [TN][KP]

    const int tid = threadIdx.x;
    const int lane = tid & 31;
    const int warp = tid >> 5;
    const int row0 = blockIdx.x * TM;

    // Load x tile: rows row-major, coalesced float4, conflict-free STS.128
    for (int idx = tid; idx < TM * 32; idx += 256) {
        int r = idx >> 5, c4 = idx & 31;
        int row = row0 + r;
        float4 g = make_float4(0.f, 0.f, 0.f, 0.f);
        if (row < NN) g = *(const float4*)(hin + (size_t)row * DD + c4 * 4);
        *(float4*)(xs + r * KP + c4 * 4) = g;
    }
    // Load W (Wl rows 0..127 -> ws rows 0..127, Wr -> 128..255), row-major
    for (int idx = tid; idx < TN * 32; idx += 256) {
        int r = idx >> 5, c4 = idx & 31;
        const float* wsrc = (r < DD) ? (Wl + (size_t)r * DD) : (Wr + (size_t)(r - DD) * DD);
        float4 g = *(const float4*)(wsrc + c4 * 4);
        *(float4*)(ws + r * KP + c4 * 4) = g;
    }
    __syncthreads();

    const int warp_m = warp >> 2;   // 0..1
    const int warp_n = warp & 3;    // 0..3
    const int lane_m = lane >> 3;   // 0..3
    const int lane_n = lane & 7;    // 0..7
    const int rbase = warp_m * 32 + lane_m * 8;   // rows rbase..rbase+7
    const int jbase = warp_n * 64 + lane_n;       // cols jbase + jj*8

    u64 acc[8][8];
#pragma unroll
    for (int i = 0; i < 8; i++)
#pragma unroll
        for (int j = 0; j < 8; j++) acc[i][j] = 0ull;

    const float* xp = xs + rbase * KP;
    const float* wp = ws + jbase * KP;

#pragma unroll 2
    for (int k = 0; k < DD; k += 4) {
        ulonglong2 a2[8], b2[8];
#pragma unroll
        for (int i = 0; i < 8; i++)
            a2[i] = *(const ulonglong2*)(xp + i * KP + k);       // octet-broadcast
#pragma unroll
        for (int j = 0; j < 8; j++)
            b2[j] = *(const ulonglong2*)(wp + j * 8 * KP + k);   // bank-stride 4
#pragma unroll
        for (int i = 0; i < 8; i++)
#pragma unroll
            for (int j = 0; j < 8; j++) {
                ffma2(acc[i][j], a2[i].x, b2[j].x);
                ffma2(acc[i][j], a2[i].y, b2[j].y);
            }
    }

    const bool isL = (warp_n < 2);
    float* outp = isL ? g_xl : g_xr;
    const int cb = jbase - (isL ? 0 : DD);
#pragma unroll
    for (int i = 0; i < 8; i++) {
        int row = row0 + rbase + i;
        if (row < NN) {
            float* orow = outp + (size_t)row * DD;
#pragma unroll
            for (int j = 0; j < 8; j++) {
                float2 s = *(float2*)&acc[i][j];
                orow[cb + j * 8] = s.x + s.y;
            }
        }
    }
}

// ---------------------------------------------------------------------------
// GATv2 aggregation, warp per destination node, online softmax single pass.
// ---------------------------------------------------------------------------
__device__ __forceinline__ float gelu_exact(float x) {
    return 0.5f * x * (1.f + erff(x * 0.70710678118654752440f));
}

__global__ void __launch_bounds__(256)
k_agg(const float* __restrict__ att,
      const float* __restrict__ bias,
      float* __restrict__ hout) {
    const int gw = (blockIdx.x * blockDim.x + threadIdx.x) >> 5;
    const int lane = threadIdx.x & 31;
    if (gw >= NN) return;
    const int d4 = lane * 4;

    const float4 xr4 = *(const float4*)(g_xr + (size_t)gw * DD + d4);
    const float4 at4 = *(const float4*)(att + d4);

    const int p0 = g_rowptr[gw];
    const int p1 = g_rowptr[gw + 1];

    float m = __int_as_float(0xff800000);  // -inf
    float denom = 0.f;
    float ax = 0.f, ay = 0.f, az = 0.f, aw = 0.f;

    for (int p = p0; p < p1; p++) {
        int s = __ldg(&g_srcs[p]);
        const float4 v = *(const float4*)(g_xl + (size_t)s * DD + d4);
        float t0 = v.x + xr4.x; t0 = t0 > 0.f ? t0 : 0.2f * t0;
        float t1 = v.y + xr4.y; t1 = t1 > 0.f ? t1 : 0.2f * t1;
        float t2 = v.z + xr4.z; t2 = t2 > 0.f ? t2 : 0.2f * t2;
        float t3 = v.w + xr4.w; t3 = t3 > 0.f ? t3 : 0.2f * t3;
        float e = t0 * at4.x + t1 * at4.y + t2 * at4.z + t3 * at4.w;
        e += __shfl_xor_sync(0xffffffffu, e, 16);
        e += __shfl_xor_sync(0xffffffffu, e, 8);
        e += __shfl_xor_sync(0xffffffffu, e, 4);
        e += __shfl_xor_sync(0xffffffffu, e, 2);
        e += __shfl_xor_sync(0xffffffffu, e, 1);

        float mn = fmaxf(m, e);
        float corr = expf(m - mn);
        float w = expf(e - mn);
        denom = denom * corr + w;
        ax = ax * corr + w * v.x;
        ay = ay * corr + w * v.y;
        az = az * corr + w * v.z;
        aw = aw * corr + w * v.w;
        m = mn;
    }

    const float inv = 1.f / denom;
    const float4 b4 = *(const float4*)(bias + d4);
    float4 o;
    o.x = gelu_exact(ax * inv + b4.x);
    o.y = gelu_exact(ay * inv + b4.y);
    o.z = gelu_exact(az * inv + b4.z);
    o.w = gelu_exact(aw * inv + b4.w);
    *(float4*)(hout + (size_t)gw * DD + d4) = o;
}

// ---------------------------------------------------------------------------
extern "C" void kernel_launch(void* const* d_in, const int* in_sizes, int n_in,
                              void* d_out, int out_size) {
    const float* x = (const float*)d_in[0];
    const void* eidx = d_in[1];
    const float* Wl[3] = {(const float*)d_in[2], (const float*)d_in[6], (const float*)d_in[10]};
    const float* Wr[3] = {(const float*)d_in[3], (const float*)d_in[7], (const float*)d_in[11]};
    const float* at[3] = {(const float*)d_in[4], (const float*)d_in[8], (const float*)d_in[12]};
    const float* bi[3] = {(const float*)d_in[5], (const float*)d_in[9], (const float*)d_in[13]};

    void* p_h_v = nullptr;
    cudaGetSymbolAddress(&p_h_v, g_h);
    float* p_h = (float*)p_h_v;

    cudaFuncSetAttribute(k_gemm, cudaFuncAttributeMaxDynamicSharedMemorySize, GEMM_SMEM);

    // Build CSR by destination (same graph for all 3 layers)
    k_detect<<<1, 32>>>(eidx);
    k_zero_cnt<<<(NN + 255) / 256, 256>>>();
    k_hist<<<(ET + 255) / 256, 256>>>(eidx);
    k_scan1<<<NBLK, SCB>>>();
    k_scan2<<<1, 32>>>();
    k_scan3<<<NBLK, SCB>>>();
    k_scatter<<<(ET + 255) / 256, 256>>>(eidx);

    for (int l = 0; l < 3; l++) {
        const float* hin = (l == 0) ? x : p_h;
        float* hout = (l == 2) ? (float*)d_out : p_h;
        k_gemm<<<(NN + TM - 1) / TM, 256, GEMM_SMEM>>>(hin, Wl[l], Wr[l]);
        k_agg<<<(NN * 32 + 255) / 256, 256>>>(at[l], bi[l], hout);
    }
}

// round 3
// speedup vs baseline: 2.2540x; 1.0950x over previous
#include <cuda_runtime.h>
#include <math.h>

#define NN 50000
#define DD 128
#define EE 800000
#define ET (EE + NN)

#define TM 64
#define TN 256
#define KP 132                      // smem row pitch (floats)
#define GEMM_SMEM ((TM + TN) * KP * 4)   // 168960 B

#define SCB 1024
#define NBLK ((NN + SCB - 1) / SCB) // 49

// Scratch (allocation-free rule: __device__ globals)
__device__ float g_xl[NN * DD];
__device__ float g_xr[NN * DD];
__device__ float g_h[NN * DD];
__device__ int g_rowptr[NN + 1];
__device__ int g_deg[NN];
__device__ int g_fill[NN];
__device__ int g_srcs[ET];
__device__ int g_part[NBLK];
__device__ int g_is64;

// ---------------------------------------------------------------------------
// init: zero counters, detect edge_index dtype, rowptr[NN]=ET      (launch 1)
// ---------------------------------------------------------------------------
__global__ void k_init(const void* e) {
    int i = blockIdx.x * blockDim.x + threadIdx.x;
    if (i < NN) { g_deg[i] = 0; g_fill[i] = 0; }
    if (i == 0) {
        const long long* p = (const long long*)e;
        int ok = 1;
        for (int q = 0; q < 16; q++) {
            long long v = p[q];
            if (v < 0 || v >= NN) ok = 0;
        }
        g_is64 = ok;
        g_rowptr[NN] = ET;
    }
}

__device__ __forceinline__ int load_idx(const void* e, long long pos, int is64) {
    return is64 ? (int)((const long long*)e)[pos] : ((const int*)e)[pos];
}

__global__ void k_hist(const void* __restrict__ eidx) {              // launch 2
    int e = blockIdx.x * blockDim.x + threadIdx.x;
    if (e >= ET) return;
    int is64 = g_is64;
    int dst = (e < EE) ? load_idx(eidx, (long long)EE + e, is64) : (e - EE);
    atomicAdd(&g_deg[dst], 1);
}

// block sums of g_deg -> g_part                                     (launch 3)
__global__ void k_scan1() {
    __shared__ int wsum[32];
    int i = blockIdx.x * SCB + threadIdx.x;
    int lane = threadIdx.x & 31, wid = threadIdx.x >> 5;
    int v = (i < NN) ? g_deg[i] : 0;
#pragma unroll
    for (int o = 1; o < 32; o <<= 1) v += __shfl_down_sync(~0u, v, o);
    if (lane == 0) wsum[wid] = v;
    __syncthreads();
    if (wid == 0) {
        int s = wsum[lane];
#pragma unroll
        for (int o = 1; o < 32; o <<= 1) s += __shfl_down_sync(~0u, s, o);
        if (lane == 0) g_part[blockIdx.x] = s;
    }
}

// per-block: base = sum(parts < bid), local exclusive scan -> rowptr (launch 4)
__global__ void k_scan2() {
    __shared__ int wsum[32];
    __shared__ int sbase;
    int i = blockIdx.x * SCB + threadIdx.x;
    int lane = threadIdx.x & 31, wid = threadIdx.x >> 5;

    if (wid == 0) {  // 1 warp sums partials of preceding blocks (NBLK=49 < 64)
        int b = 0;
        for (int t = lane; t < NBLK; t += 32)
            if (t < blockIdx.x) b += g_part[t];
#pragma unroll
        for (int o = 1; o < 32; o <<= 1) b += __shfl_down_sync(~0u, b, o);
        if (lane == 0) sbase = b;
    }

    int v0 = (i < NN) ? g_deg[i] : 0;
    int v = v0;
#pragma unroll
    for (int o = 1; o < 32; o <<= 1) {
        int n = __shfl_up_sync(~0u, v, o);
        if (lane >= o) v += n;
    }
    if (lane == 31) wsum[wid] = v;
    __syncthreads();
    if (wid == 0) {
        int s = (lane < 32) ? wsum[lane] : 0;
#pragma unroll
        for (int o = 1; o < 32; o <<= 1) {
            int n = __shfl_up_sync(~0u, s, o);
            if (lane >= o) s += n;
        }
        wsum[lane] = s;
    }
    __syncthreads();
    int excl = v - v0 + (wid ? wsum[wid - 1] : 0);
    if (i < NN) g_rowptr[i] = sbase + excl;
}

__global__ void k_scatter(const void* __restrict__ eidx) {           // launch 5
    int e = blockIdx.x * blockDim.x + threadIdx.x;
    if (e >= ET) return;
    int is64 = g_is64;
    int s, d;
    if (e < EE) {
        s = load_idx(eidx, e, is64);
        d = load_idx(eidx, (long long)EE + e, is64);
    } else {
        s = d = e - EE;
    }
    int pos = atomicAdd(&g_fill[d], 1);
    g_srcs[g_rowptr[d] + pos] = s;
}

// ---------------------------------------------------------------------------
// Fused GEMM: xl = h @ Wl^T, xr = h @ Wr^T. f32x2 packed FFMA.
// Thread rows: base + 4*i (lane_m stride 1 row => conflict-free A loads).
// ---------------------------------------------------------------------------
typedef unsigned long long u64;

__device__ __forceinline__ void ffma2(u64& acc, u64 a, u64 b) {
    asm("fma.rn.f32x2 %0, %1, %2, %0;" : "+l"(acc) : "l"(a), "l"(b));
}

__global__ void __launch_bounds__(256, 1)
k_gemm(const float* __restrict__ hin,
       const float* __restrict__ Wl,
       const float* __restrict__ Wr) {
    extern __shared__ float sm[];
    float* xs = sm;             // [TM][KP]
    float* ws = sm + TM * KP;   // [TN][KP]

    const int tid = threadIdx.x;
    const int lane = tid & 31;
    const int warp = tid >> 5;
    const int row0 = blockIdx.x * TM;

    for (int idx = tid; idx < TM * 32; idx += 256) {
        int r = idx >> 5, c4 = idx & 31;
        int row = row0 + r;
        float4 g = make_float4(0.f, 0.f, 0.f, 0.f);
        if (row < NN) g = *(const float4*)(hin + (size_t)row * DD + c4 * 4);
        *(float4*)(xs + r * KP + c4 * 4) = g;
    }
    for (int idx = tid; idx < TN * 32; idx += 256) {
        int r = idx >> 5, c4 = idx & 31;
        const float* wsrc = (r < DD) ? (Wl + (size_t)r * DD) : (Wr + (size_t)(r - DD) * DD);
        float4 g = *(const float4*)(wsrc + c4 * 4);
        *(float4*)(ws + r * KP + c4 * 4) = g;
    }
    __syncthreads();

    const int warp_m = warp >> 2;   // 0..1
    const int warp_n = warp & 3;    // 0..3
    const int lane_m = lane >> 3;   // 0..3
    const int lane_n = lane & 7;    // 0..7
    const int rbase = warp_m * 32 + lane_m;   // rows rbase + 4*i
    const int jbase = warp_n * 64 + lane_n;   // cols jbase + 8*j

    u64 acc[8][8];
#pragma unroll
    for (int i = 0; i < 8; i++)
#pragma unroll
        for (int j = 0; j < 8; j++) acc[i][j] = 0ull;

    const float* xp = xs + rbase * KP;
    const float* wp = ws + jbase * KP;

#pragma unroll 2
    for (int k = 0; k < DD; k += 4) {
        ulonglong2 a2[8], b2[8];
#pragma unroll
        for (int i = 0; i < 8; i++)
            a2[i] = *(const ulonglong2*)(xp + i * 4 * KP + k);
#pragma unroll
        for (int j = 0; j < 8; j++)
            b2[j] = *(const ulonglong2*)(wp + j * 8 * KP + k);
#pragma unroll
        for (int i = 0; i < 8; i++)
#pragma unroll
            for (int j = 0; j < 8; j++) {
                ffma2(acc[i][j], a2[i].x, b2[j].x);
                ffma2(acc[i][j], a2[i].y, b2[j].y);
            }
    }

    const bool isL = (warp_n < 2);
    float* outp = isL ? g_xl : g_xr;
    const int cb = jbase - (isL ? 0 : DD);
#pragma unroll
    for (int i = 0; i < 8; i++) {
        int row = row0 + rbase + i * 4;
        if (row < NN) {
            float* orow = outp + (size_t)row * DD;
#pragma unroll
            for (int j = 0; j < 8; j++) {
                float2 s = *(float2*)&acc[i][j];
                orow[cb + j * 8] = s.x + s.y;
            }
        }
    }
}

// ---------------------------------------------------------------------------
// GATv2 aggregation: warp/node, online softmax, 4-edge ILP.
// ---------------------------------------------------------------------------
__device__ __forceinline__ float gelu_exact(float x) {
    return 0.5f * x * (1.f + erff(x * 0.70710678118654752440f));
}

__device__ __forceinline__ float wsum32(float e) {
    e += __shfl_xor_sync(0xffffffffu, e, 16);
    e += __shfl_xor_sync(0xffffffffu, e, 8);
    e += __shfl_xor_sync(0xffffffffu, e, 4);
    e += __shfl_xor_sync(0xffffffffu, e, 2);
    e += __shfl_xor_sync(0xffffffffu, e, 1);
    return e;
}

__global__ void __launch_bounds__(256)
k_agg(const float* __restrict__ att,
      const float* __restrict__ bias,
      float* __restrict__ hout) {
    const int gw = (blockIdx.x * blockDim.x + threadIdx.x) >> 5;
    const int lane = threadIdx.x & 31;
    if (gw >= NN) return;
    const int d4 = lane * 4;

    const float4 xr4 = *(const float4*)(g_xr + (size_t)gw * DD + d4);
    const float4 at4 = *(const float4*)(att + d4);

    const int p0 = g_rowptr[gw];
    const int p1 = g_rowptr[gw + 1];

    float m = __int_as_float(0xff800000);  // -inf
    float denom = 0.f;
    float ax = 0.f, ay = 0.f, az = 0.f, aw = 0.f;

    int p = p0;
    for (; p + 4 <= p1; p += 4) {
        float4 v[4];
        float e[4];
#pragma unroll
        for (int q = 0; q < 4; q++) {
            int s = __ldg(&g_srcs[p + q]);
            v[q] = *(const float4*)(g_xl + (size_t)s * DD + d4);
            float t0 = v[q].x + xr4.x; t0 = t0 > 0.f ? t0 : 0.2f * t0;
            float t1 = v[q].y + xr4.y; t1 = t1 > 0.f ? t1 : 0.2f * t1;
            float t2 = v[q].z + xr4.z; t2 = t2 > 0.f ? t2 : 0.2f * t2;
            float t3 = v[q].w + xr4.w; t3 = t3 > 0.f ? t3 : 0.2f * t3;
            e[q] = t0 * at4.x + t1 * at4.y + t2 * at4.z + t3 * at4.w;
        }
#pragma unroll
        for (int q = 0; q < 4; q++) e[q] = wsum32(e[q]);
#pragma unroll
        for (int q = 0; q < 4; q++) {
            float mn = fmaxf(m, e[q]);
            float corr = __expf(m - mn);
            float w = __expf(e[q] - mn);
            denom = denom * corr + w;
            ax = ax * corr + w * v[q].x;
            ay = ay * corr + w * v[q].y;
            az = az * corr + w * v[q].z;
            aw = aw * corr + w * v[q].w;
            m = mn;
        }
    }
    for (; p < p1; p++) {
        int s = __ldg(&g_srcs[p]);
        const float4 vv = *(const float4*)(g_xl + (size_t)s * DD + d4);
        float t0 = vv.x + xr4.x; t0 = t0 > 0.f ? t0 : 0.2f * t0;
        float t1 = vv.y + xr4.y; t1 = t1 > 0.f ? t1 : 0.2f * t1;
        float t2 = vv.z + xr4.z; t2 = t2 > 0.f ? t2 : 0.2f * t2;
        float t3 = vv.w + xr4.w; t3 = t3 > 0.f ? t3 : 0.2f * t3;
        float e = wsum32(t0 * at4.x + t1 * at4.y + t2 * at4.z + t3 * at4.w);
        float mn = fmaxf(m, e);
        float corr = __expf(m - mn);
        float w = __expf(e - mn);
        denom = denom * corr + w;
        ax = ax * corr + w * vv.x;
        ay = ay * corr + w * vv.y;
        az = az * corr + w * vv.z;
        aw = aw * corr + w * vv.w;
        m = mn;
    }

    const float inv = 1.f / denom;
    const float4 b4 = *(const float4*)(bias + d4);
    float4 o;
    o.x = gelu_exact(ax * inv + b4.x);
    o.y = gelu_exact(ay * inv + b4.y);
    o.z = gelu_exact(az * inv + b4.z);
    o.w = gelu_exact(aw * inv + b4.w);
    *(float4*)(hout + (size_t)gw * DD + d4) = o;
}

// ---------------------------------------------------------------------------
extern "C" void kernel_launch(void* const* d_in, const int* in_sizes, int n_in,
                              void* d_out, int out_size) {
    const float* x = (const float*)d_in[0];
    const void* eidx = d_in[1];
    const float* Wl[3] = {(const float*)d_in[2], (const float*)d_in[6], (const float*)d_in[10]};
    const float* Wr[3] = {(const float*)d_in[3], (const float*)d_in[7], (const float*)d_in[11]};
    const float* at[3] = {(const float*)d_in[4], (const float*)d_in[8], (const float*)d_in[12]};
    const float* bi[3] = {(const float*)d_in[5], (const float*)d_in[9], (const float*)d_in[13]};

    void* p_h_v = nullptr;
    cudaGetSymbolAddress(&p_h_v, g_h);
    float* p_h = (float*)p_h_v;

    cudaFuncSetAttribute(k_gemm, cudaFuncAttributeMaxDynamicSharedMemorySize, GEMM_SMEM);

    // CSR build: launches 1..5, so launch 6 (profiled: -s 5 -c 1) is k_gemm
    k_init<<<(NN + 255) / 256, 256>>>(eidx);
    k_hist<<<(ET + 255) / 256, 256>>>(eidx);
    k_scan1<<<NBLK, SCB>>>();
    k_scan2<<<NBLK, SCB>>>();
    k_scatter<<<(ET + 255) / 256, 256>>>(eidx);

    for (int l = 0; l < 3; l++) {
        const float* hin = (l == 0) ? x : p_h;
        float* hout = (l == 2) ? (float*)d_out : p_h;
        k_gemm<<<(NN + TM - 1) / TM, 256, GEMM_SMEM>>>(hin, Wl[l], Wr[l]);
        k_agg<<<(NN * 32 + 255) / 256, 256>>>(at[l], bi[l], hout);
    }
}